// round 11
// baseline (speedup 1.0000x reference)
#include <cuda_runtime.h>

#define BATCH 512
#define NROWS 256
#define NVECS 8
#define VEC   128
#define DIM   1024
#define EPSF  1e-8f

#define BM 128
#define BR 64
#define PAD (VEC + 4)

#define NDOT   128     // dot CTAs (4 bx * 4 by * 8 seg), all resident in wave 1
#define NCOMBO 2048    // combo CTAs (512 b * 4 r-chunks)
#define RCHUNK 64

// Scratch: relu'd cosine sims, layout [seg][b][r].
__device__ float g_cos[NVECS * BATCH * NROWS];
// Per tile-group (bx*4+by) flags. Self-resetting across graph replays.
__device__ int g_ready[16];   // segs completed for this (128b x 64r) group
__device__ int g_done[16];    // combo CTAs finished for this group

// ---------------------------------------------------------------------------
// Fused kernel. CTAs 0..127: segmented GEMM (+fused norms) -> g_cos, then
// release their tile-group flag. CTAs 128..2175: spin on their group's flag,
// then expand 256 NAND-combos per (b,r) and stream-store 134 MB of output.
// Overlap: DRAM write drain runs concurrently with the tail of the GEMM and
// starts immediately per-group instead of after a kernel boundary.
// ---------------------------------------------------------------------------
__global__ __launch_bounds__(256) void fused_kernel(const float* __restrict__ query,
                                                    const float* __restrict__ weight,
                                                    float* __restrict__ out) {
    extern __shared__ float smem[];
    int cta = blockIdx.x;
    int tid = threadIdx.x;

    if (cta < NDOT) {
        // ================= DOT ROLE =================
        float (*qs)[PAD] = (float (*)[PAD])smem;                 // 128 x 132
        float (*ws)[PAD] = (float (*)[PAD])(smem + BM * PAD);    // 64 x 132
        float* qn = smem + (BM + BR) * PAD;                      // 128
        float* wn = qn + BM;                                     // 64

        int seg = cta & 7;
        int bx  = (cta >> 3) & 3;
        int by  = cta >> 5;
        int bbase = bx * BM;
        int rbase = by * BR;
        int tx = tid & 15;    // r micro-index
        int ty = tid >> 4;    // b micro-index (0..15)

        // Tile loads: float4 gmem -> float4 smem (warp = one row, coalesced).
        for (int i = tid; i < BM * 32; i += 256) {
            int row = i >> 5, c4 = i & 31;
            float4 v = *(const float4*)(query + (size_t)(bbase + row) * DIM + seg * VEC + c4 * 4);
            *(float4*)&qs[row][c4 * 4] = v;
        }
        for (int i = tid; i < BR * 32; i += 256) {
            int row = i >> 5, c4 = i & 31;
            float4 v = *(const float4*)(weight + (size_t)(rbase + row) * DIM + seg * VEC + c4 * 4);
            *(float4*)&ws[row][c4 * 4] = v;
        }
        __syncthreads();

        // Fused inverse norms from smem tiles.
        if (tid < BM) {
            float s = 0.0f;
#pragma unroll 8
            for (int k = 0; k < VEC; k += 4) {
                float4 v = *(const float4*)&qs[tid][k];
                s = fmaf(v.x, v.x, s); s = fmaf(v.y, v.y, s);
                s = fmaf(v.z, v.z, s); s = fmaf(v.w, v.w, s);
            }
            qn[tid] = 1.0f / fmaxf(sqrtf(s), EPSF);
        } else if (tid < BM + BR) {
            int row = tid - BM;
            float s = 0.0f;
#pragma unroll 8
            for (int k = 0; k < VEC; k += 4) {
                float4 v = *(const float4*)&ws[row][k];
                s = fmaf(v.x, v.x, s); s = fmaf(v.y, v.y, s);
                s = fmaf(v.z, v.z, s); s = fmaf(v.w, v.w, s);
            }
            wn[row] = 1.0f / fmaxf(sqrtf(s), EPSF);
        }
        __syncthreads();

        // 8x4 micro-tile GEMM: 12 LDS.128 per 128 FMA -> FMA-pipe bound.
        float acc[8][4] = {};
#pragma unroll 1
        for (int k = 0; k < VEC; k += 4) {
            float4 qv[8], wv[4];
#pragma unroll
            for (int i = 0; i < 8; i++) qv[i] = *(const float4*)&qs[ty + 16 * i][k];
#pragma unroll
            for (int j = 0; j < 4; j++) wv[j] = *(const float4*)&ws[tx + 16 * j][k];
#pragma unroll
            for (int i = 0; i < 8; i++)
#pragma unroll
                for (int j = 0; j < 4; j++) {
                    acc[i][j] = fmaf(qv[i].x, wv[j].x, acc[i][j]);
                    acc[i][j] = fmaf(qv[i].y, wv[j].y, acc[i][j]);
                    acc[i][j] = fmaf(qv[i].z, wv[j].z, acc[i][j]);
                    acc[i][j] = fmaf(qv[i].w, wv[j].w, acc[i][j]);
                }
        }

        // Epilogue: scale, relu, coalesced store to [seg][b][r].
        float* dst = g_cos + (size_t)seg * BATCH * NROWS;
#pragma unroll
        for (int i = 0; i < 8; i++) {
            int b = bbase + ty + 16 * i;
            float qi = qn[ty + 16 * i];
#pragma unroll
            for (int j = 0; j < 4; j++) {
                int r = rbase + tx + 16 * j;
                float v = acc[i][j] * qi * wn[tx + 16 * j];
                dst[(size_t)b * NROWS + r] = fmaxf(v, 0.0f);
            }
        }

        // Release: stores -> fence -> barrier -> flag add (device-scope).
        __threadfence();
        __syncthreads();
        if (tid == 0) atomicAdd(&g_ready[bx * 4 + by], 1);

    } else {
        // ================= COMBO ROLE =================
        float (*cs)[NVECS] = (float (*)[NVECS])smem;   // 64 x 8 = 2 KB used

        int c  = cta - NDOT;
        int b  = c >> 2;
        int rq = c & 3;
        int r0 = rq * RCHUNK;
        int grp = (b >> 7) * 4 + rq;

        // Acquire: spin until all 8 seg tiles of this group are published.
        if (tid == 0) {
            while (atomicAdd(&g_ready[grp], 0) < 8) __nanosleep(128);
        }
        __syncthreads();
        __threadfence();

        // Load this chunk's cos values: 8 contiguous 256B runs (one per seg).
        for (int i = tid; i < RCHUNK * NVECS; i += 256) {
            int seg = i >> 6;
            int rr  = i & 63;
            cs[rr][seg] = g_cos[(size_t)seg * BATCH * NROWS + (size_t)b * NROWS + r0 + rr];
        }
        __syncthreads();

        int sub   = tid & 63;   // combo quad: combos [4*sub, 4*sub+3]
        int rlane = tid >> 6;   // 0..3

        // Per-bit select constants: (bit? 1-v : v) == fmaf(sgn, v, off).
        float sgn[6], off[6];
#pragma unroll
        for (int j = 0; j < 6; j++) {
            int bit = (sub >> j) & 1;
            sgn[j] = bit ? -1.0f : 1.0f;
            off[j] = bit ? 1.0f : 0.0f;
        }

        float* ob = out + (size_t)b * NROWS * 256 + (size_t)r0 * 256;

#pragma unroll
        for (int rg = 0; rg < RCHUNK / 4; rg++) {
            int r = rg * 4 + rlane;
            float4 cA = *(const float4*)&cs[r][0];   // c0..c3 (LDS.128, bcast)
            float4 cB = *(const float4*)&cs[r][4];   // c4..c7

            float t2 = fmaf(sgn[0], cA.z, off[0]);
            float t3 = fmaf(sgn[1], cA.w, off[1]);
            float t4 = fmaf(sgn[2], cB.x, off[2]);
            float t5 = fmaf(sgn[3], cB.y, off[3]);
            float t6 = fmaf(sgn[4], cB.z, off[4]);
            float t7 = fmaf(sgn[5], cB.w, off[5]);
            float p  = ((t2 * t3) * (t4 * t5)) * (t6 * t7);

            float c0 = cA.x, c1 = cA.y;
            float n0 = 1.0f - c0;
            float pc1 = p * c1;
            float pn1 = p * (1.0f - c1);
            float4 o;
            o.x = pc1 * c0;    // combo bits (0,0)
            o.y = pc1 * n0;    // (1,0)
            o.z = pn1 * c0;    // (0,1)
            o.w = pn1 * n0;    // (1,1)

            __stcs((float4*)(ob + (size_t)r * 256) + sub, o);
        }

        // Cleanup for the next graph replay: last combo CTA of the group
        // (out of 128) zeroes both counters. All readers have passed the
        // spin by construction, so plain stores are race-free.
        __syncthreads();
        if (tid == 0) {
            int old = atomicAdd(&g_done[grp], 1);
            if (old == 127) {
                g_done[grp]  = 0;
                g_ready[grp] = 0;
                __threadfence();
            }
        }
    }
}

// ---------------------------------------------------------------------------
extern "C" void kernel_launch(void* const* d_in, const int* in_sizes, int n_in,
                              void* d_out, int out_size) {
    const float* query  = (const float*)d_in[0];   // [512, 1024]
    const float* weight = (const float*)d_in[1];   // [256, 1024]
    float* out = (float*)d_out;                    // [512, 256, 256]

    const int smem_bytes = ((BM + BR) * PAD + BM + BR) * (int)sizeof(float); // ~102 KB
    (void)cudaFuncSetAttribute(fused_kernel,
                               cudaFuncAttributeMaxDynamicSharedMemorySize,
                               smem_bytes);

    fused_kernel<<<NDOT + NCOMBO, 256, smem_bytes>>>(query, weight, out);
}

// round 13
// speedup vs baseline: 1.2142x; 1.2142x over previous
#include <cuda_runtime.h>

#define BATCH 512
#define NROWS 256
#define NVECS 8
#define VEC   128
#define DIM   1024
#define EPSF  1e-8f

#define BM 128
#define BR 64
#define PAD (VEC + 4)

#define NDOT   128     // dot CTAs (8 seg * 4 bx * 4 by), all resident in wave 1
#define NCOMBO 2048    // combo CTAs (512 b * 4 r-chunks)
#define RCHUNK 64

// Scratch: relu'd cosine sims, layout [seg][b][r].
__device__ float g_cos[NVECS * BATCH * NROWS];
// Per tile-group (bx*4+by) flags. Self-resetting across graph replays.
__device__ int g_ready[16];   // segs completed for this (128b x 64r) group
__device__ int g_done[16];    // combo CTAs finished for this group

// ---------------------------------------------------------------------------
// Kernel 1 (PDL primary): segmented GEMM + fused norms -> g_cos, then release
// per-tile-group flag. 512 threads, 4x4 micro-tile, software-pipelined k-loop.
// Triggers programmatic completion at entry so the combo kernel co-runs.
// ---------------------------------------------------------------------------
__global__ __launch_bounds__(512) void dot_kernel(const float* __restrict__ query,
                                                  const float* __restrict__ weight) {
    extern __shared__ float smem[];
    float (*qs)[PAD] = (float (*)[PAD])smem;                 // 128 x 132
    float (*ws)[PAD] = (float (*)[PAD])(smem + BM * PAD);    // 64 x 132
    float* qn = smem + (BM + BR) * PAD;                      // 128
    float* wn = qn + BM;                                     // 64

    int cta = blockIdx.x;
    int tid = threadIdx.x;

#if __CUDA_ARCH__ >= 900
    if (tid == 0) cudaTriggerProgrammaticLaunchCompletion();
#endif

    int seg = cta & 7;
    int bx  = (cta >> 3) & 3;
    int by  = cta >> 5;
    int bbase = bx * BM;
    int rbase = by * BR;
    int tx = tid & 15;    // r micro-index
    int ty = tid >> 4;    // b micro-index (0..31)

    // Tile loads: float4 gmem -> float4 smem.
    for (int i = tid; i < BM * 32; i += 512) {
        int row = i >> 5, c4 = i & 31;
        float4 v = *(const float4*)(query + (size_t)(bbase + row) * DIM + seg * VEC + c4 * 4);
        *(float4*)&qs[row][c4 * 4] = v;
    }
    for (int i = tid; i < BR * 32; i += 512) {
        int row = i >> 5, c4 = i & 31;
        float4 v = *(const float4*)(weight + (size_t)(rbase + row) * DIM + seg * VEC + c4 * 4);
        *(float4*)&ws[row][c4 * 4] = v;
    }
    __syncthreads();

    // Fused inverse norms from smem tiles.
    if (tid < BM) {
        float s = 0.0f;
#pragma unroll 8
        for (int k = 0; k < VEC; k += 4) {
            float4 v = *(const float4*)&qs[tid][k];
            s = fmaf(v.x, v.x, s); s = fmaf(v.y, v.y, s);
            s = fmaf(v.z, v.z, s); s = fmaf(v.w, v.w, s);
        }
        qn[tid] = 1.0f / fmaxf(sqrtf(s), EPSF);
    } else if (tid < BM + BR) {
        int row = tid - BM;
        float s = 0.0f;
#pragma unroll 8
        for (int k = 0; k < VEC; k += 4) {
            float4 v = *(const float4*)&ws[row][k];
            s = fmaf(v.x, v.x, s); s = fmaf(v.y, v.y, s);
            s = fmaf(v.z, v.z, s); s = fmaf(v.w, v.w, s);
        }
        wn[row] = 1.0f / fmaxf(sqrtf(s), EPSF);
    }
    __syncthreads();

    // Software-pipelined 4x4 micro-tile GEMM: load k+4 while computing k.
    float acc[4][4] = {};
    float4 qva[4], wva[4], qvb[4], wvb[4];
#pragma unroll
    for (int i = 0; i < 4; i++) qva[i] = *(const float4*)&qs[ty + 32 * i][0];
#pragma unroll
    for (int j = 0; j < 4; j++) wva[j] = *(const float4*)&ws[tx + 16 * j][0];

#define FMA16(QV, WV)                                              \
    _Pragma("unroll")                                              \
    for (int i = 0; i < 4; i++)                                    \
        _Pragma("unroll")                                          \
        for (int j = 0; j < 4; j++) {                              \
            acc[i][j] = fmaf(QV[i].x, WV[j].x, acc[i][j]);         \
            acc[i][j] = fmaf(QV[i].y, WV[j].y, acc[i][j]);         \
            acc[i][j] = fmaf(QV[i].z, WV[j].z, acc[i][j]);         \
            acc[i][j] = fmaf(QV[i].w, WV[j].w, acc[i][j]);         \
        }

#pragma unroll
    for (int k = 0; k < VEC; k += 8) {
        // load k+4 into B while computing A(k)
#pragma unroll
        for (int i = 0; i < 4; i++) qvb[i] = *(const float4*)&qs[ty + 32 * i][k + 4];
#pragma unroll
        for (int j = 0; j < 4; j++) wvb[j] = *(const float4*)&ws[tx + 16 * j][k + 4];
        FMA16(qva, wva)
        // load k+8 into A while computing B(k+4)
        if (k + 8 < VEC) {
#pragma unroll
            for (int i = 0; i < 4; i++) qva[i] = *(const float4*)&qs[ty + 32 * i][k + 8];
#pragma unroll
            for (int j = 0; j < 4; j++) wva[j] = *(const float4*)&ws[tx + 16 * j][k + 8];
        }
        FMA16(qvb, wvb)
    }
#undef FMA16

    // Epilogue: scale, relu, coalesced store to [seg][b][r].
    float* dst = g_cos + (size_t)seg * BATCH * NROWS;
#pragma unroll
    for (int i = 0; i < 4; i++) {
        int b = bbase + ty + 32 * i;
        float qi = qn[ty + 32 * i];
#pragma unroll
        for (int j = 0; j < 4; j++) {
            int r = rbase + tx + 16 * j;
            float v = acc[i][j] * qi * wn[tx + 16 * j];
            dst[(size_t)b * NROWS + r] = fmaxf(v, 0.0f);
        }
    }

    // Release: stores -> fence -> barrier -> flag add (device scope).
    __threadfence();
    __syncthreads();
    if (tid == 0) atomicAdd(&g_ready[bx * 4 + by], 1);
}

// ---------------------------------------------------------------------------
// Kernel 2 (PDL secondary): combo-product expansion. Spins on its tile-group
// flag, then streams 134 MB of output. Small smem + capped regs -> high occ.
// ---------------------------------------------------------------------------
__global__ __launch_bounds__(256, 8) void combo_kernel(float* __restrict__ out) {
    __shared__ float cs[RCHUNK][NVECS];   // 2 KB

    int c   = blockIdx.x;
    int b   = c >> 2;
    int rq  = c & 3;
    int r0  = rq * RCHUNK;
    int grp = (b >> 7) * 4 + rq;
    int tid = threadIdx.x;

    // Acquire: wait for all 8 seg tiles of this group.
    if (tid == 0) {
        while (atomicAdd(&g_ready[grp], 0) < 8) __nanosleep(128);
    }
    __syncthreads();
    __threadfence();

    // Load this chunk's cos values: 8 contiguous 256B runs (one per seg).
    for (int i = tid; i < RCHUNK * NVECS; i += 256) {
        int seg = i >> 6;
        int rr  = i & 63;
        cs[rr][seg] = g_cos[(size_t)seg * BATCH * NROWS + (size_t)b * NROWS + r0 + rr];
    }
    __syncthreads();

    int sub   = tid & 63;   // combo quad: combos [4*sub, 4*sub+3]
    int rlane = tid >> 6;   // 0..3

    // Per-bit select constants: (bit? 1-v : v) == fmaf(sgn, v, off).
    float sgn[6], off[6];
#pragma unroll
    for (int j = 0; j < 6; j++) {
        int bit = (sub >> j) & 1;
        sgn[j] = bit ? -1.0f : 1.0f;
        off[j] = bit ? 1.0f : 0.0f;
    }

    float* ob = out + (size_t)b * NROWS * 256 + (size_t)r0 * 256;

#pragma unroll
    for (int rg = 0; rg < RCHUNK / 4; rg++) {
        int r = rg * 4 + rlane;
        float4 cA = *(const float4*)&cs[r][0];   // c0..c3
        float4 cB = *(const float4*)&cs[r][4];   // c4..c7

        float t2 = fmaf(sgn[0], cA.z, off[0]);
        float t3 = fmaf(sgn[1], cA.w, off[1]);
        float t4 = fmaf(sgn[2], cB.x, off[2]);
        float t5 = fmaf(sgn[3], cB.y, off[3]);
        float t6 = fmaf(sgn[4], cB.z, off[4]);
        float t7 = fmaf(sgn[5], cB.w, off[5]);
        float p  = ((t2 * t3) * (t4 * t5)) * (t6 * t7);

        float c0 = cA.x, c1 = cA.y;
        float n0 = 1.0f - c0;
        float pc1 = p * c1;
        float pn1 = p * (1.0f - c1);
        float4 o;
        o.x = pc1 * c0;    // combo bits (0,0)
        o.y = pc1 * n0;    // (1,0)
        o.z = pn1 * c0;    // (0,1)
        o.w = pn1 * n0;    // (1,1)

        __stcs((float4*)(ob + (size_t)r * 256) + sub, o);
    }

    // Cleanup for the next graph replay: last combo CTA of the group zeroes
    // both counters (all 128 readers have passed the spin by then).
    __syncthreads();
    if (tid == 0) {
        int old = atomicAdd(&g_done[grp], 1);
        if (old == 127) {
            g_done[grp]  = 0;
            g_ready[grp] = 0;
            __threadfence();
        }
    }
}

// ---------------------------------------------------------------------------
extern "C" void kernel_launch(void* const* d_in, const int* in_sizes, int n_in,
                              void* d_out, int out_size) {
    const float* query  = (const float*)d_in[0];   // [512, 1024]
    const float* weight = (const float*)d_in[1];   // [256, 1024]
    float* out = (float*)d_out;                    // [512, 256, 256]

    const int dot_smem = ((BM + BR) * PAD + BM + BR) * (int)sizeof(float); // ~102 KB
    (void)cudaFuncSetAttribute(dot_kernel,
                               cudaFuncAttributeMaxDynamicSharedMemorySize,
                               dot_smem);

    // Primary: plain launch.
    dot_kernel<<<NDOT, 512, dot_smem>>>(query, weight);

    // Secondary: programmatic dependent launch -> co-runs with dot, gated by
    // per-group flags. Falls back to a plain (serialized) launch on error.
    cudaLaunchConfig_t cfg = {};
    cfg.gridDim  = dim3(NCOMBO);
    cfg.blockDim = dim3(256);
    cfg.dynamicSmemBytes = 0;
    cfg.stream = 0;
    cudaLaunchAttribute attr[1];
    attr[0].id = cudaLaunchAttributeProgrammaticStreamSerialization;
    attr[0].val.programmaticStreamSerializationAllowed = 1;
    cfg.attrs = attr;
    cfg.numAttrs = 1;
    cudaError_t e = cudaLaunchKernelEx(&cfg, combo_kernel, out);
    if (e != cudaSuccess) {
        combo_kernel<<<NCOMBO, 256>>>(out);
    }
}

// round 15
// speedup vs baseline: 1.3079x; 1.0772x over previous
#include <cuda_runtime.h>

#define BATCH 512
#define NROWS 256
#define NVECS 8
#define VEC   128
#define DIM   1024
#define EPSF  1e-8f

#define BM 64
#define BR 64
#define PAD (VEC + 4)

#define NDOT    128    // persistent dot CTAs, 2 rounds of 128 tiles each
#define NTILES  256    // 32 groups x 8 segs
#define NGROUPS 32     // (b-chunk 64) x (r-chunk 64)
#define NCOMBO  2048   // combo CTAs (512 b * 4 r-chunks)
#define RCHUNK  64

// Scratch: relu'd cosine sims, layout [seg][b][r].
__device__ float g_cos[NVECS * BATCH * NROWS];
// Per-group flags (group = bx*4 + by, bx: b/64, by: r/64). Self-resetting.
__device__ int g_ready[NGROUPS];   // seg tiles completed for this group (target 8)
__device__ int g_done[NGROUPS];    // combo CTAs finished for this group (64 -> reset)

// ---------------------------------------------------------------------------
// Kernel 1 (PDL primary): persistent segmented GEMM. 128 CTAs x 2 rounds.
// Round 0 computes groups 0-15 (released ~halfway), round 1 groups 16-31.
// 256 threads, 4x4 micro-tile, software-pipelined k-loop, fused norms.
// ---------------------------------------------------------------------------
__global__ __launch_bounds__(256) void dot_kernel(const float* __restrict__ query,
                                                  const float* __restrict__ weight) {
    extern __shared__ float smem[];
    float (*qs)[PAD] = (float (*)[PAD])smem;                 // 64 x 132
    float (*ws)[PAD] = (float (*)[PAD])(smem + BM * PAD);    // 64 x 132
    float* qn = smem + (BM + BR) * PAD;                      // 64
    float* wn = qn + BM;                                     // 64

    int cta = blockIdx.x;
    int tid = threadIdx.x;

#if __CUDA_ARCH__ >= 900
    if (tid == 0) cudaTriggerProgrammaticLaunchCompletion();
#endif

    int tx = tid & 15;    // r micro-index
    int ty = tid >> 4;    // b micro-index

#pragma unroll 1
    for (int round = 0; round < 2; round++) {
        int tile = round * NDOT + cta;    // group-major: tile = g*8 + seg
        int g    = tile >> 3;             // 0..31
        int seg  = tile & 7;
        int bbase = (g >> 2) * BM;        // b-chunk
        int rbase = (g & 3) * BR;         // r-chunk

        if (round) __syncthreads();       // protect smem reuse across rounds

        // Tile loads: float4 gmem -> float4 smem (warp = half row, coalesced).
        for (int i = tid; i < BM * 32; i += 256) {
            int row = i >> 5, c4 = i & 31;
            float4 v = *(const float4*)(query + (size_t)(bbase + row) * DIM + seg * VEC + c4 * 4);
            *(float4*)&qs[row][c4 * 4] = v;
        }
        for (int i = tid; i < BR * 32; i += 256) {
            int row = i >> 5, c4 = i & 31;
            float4 v = *(const float4*)(weight + (size_t)(rbase + row) * DIM + seg * VEC + c4 * 4);
            *(float4*)&ws[row][c4 * 4] = v;
        }
        __syncthreads();

        // Fused inverse norms from smem tiles.
        if (tid < BM) {
            float s = 0.0f;
#pragma unroll 8
            for (int k = 0; k < VEC; k += 4) {
                float4 v = *(const float4*)&qs[tid][k];
                s = fmaf(v.x, v.x, s); s = fmaf(v.y, v.y, s);
                s = fmaf(v.z, v.z, s); s = fmaf(v.w, v.w, s);
            }
            qn[tid] = 1.0f / fmaxf(sqrtf(s), EPSF);
        } else if (tid < BM + BR) {
            int row = tid - BM;
            float s = 0.0f;
#pragma unroll 8
            for (int k = 0; k < VEC; k += 4) {
                float4 v = *(const float4*)&ws[row][k];
                s = fmaf(v.x, v.x, s); s = fmaf(v.y, v.y, s);
                s = fmaf(v.z, v.z, s); s = fmaf(v.w, v.w, s);
            }
            wn[row] = 1.0f / fmaxf(sqrtf(s), EPSF);
        }
        __syncthreads();

        // Software-pipelined 4x4 micro-tile GEMM.
        float acc[4][4] = {};
        float4 qva[4], wva[4], qvb[4], wvb[4];
#pragma unroll
        for (int i = 0; i < 4; i++) qva[i] = *(const float4*)&qs[ty + 16 * i][0];
#pragma unroll
        for (int j = 0; j < 4; j++) wva[j] = *(const float4*)&ws[tx + 16 * j][0];

#define FMA16(QV, WV)                                              \
        _Pragma("unroll")                                          \
        for (int i = 0; i < 4; i++)                                \
            _Pragma("unroll")                                      \
            for (int j = 0; j < 4; j++) {                          \
                acc[i][j] = fmaf(QV[i].x, WV[j].x, acc[i][j]);     \
                acc[i][j] = fmaf(QV[i].y, WV[j].y, acc[i][j]);     \
                acc[i][j] = fmaf(QV[i].z, WV[j].z, acc[i][j]);     \
                acc[i][j] = fmaf(QV[i].w, WV[j].w, acc[i][j]);     \
            }

#pragma unroll
        for (int k = 0; k < VEC; k += 8) {
#pragma unroll
            for (int i = 0; i < 4; i++) qvb[i] = *(const float4*)&qs[ty + 16 * i][k + 4];
#pragma unroll
            for (int j = 0; j < 4; j++) wvb[j] = *(const float4*)&ws[tx + 16 * j][k + 4];
            FMA16(qva, wva)
            if (k + 8 < VEC) {
#pragma unroll
                for (int i = 0; i < 4; i++) qva[i] = *(const float4*)&qs[ty + 16 * i][k + 8];
#pragma unroll
                for (int j = 0; j < 4; j++) wva[j] = *(const float4*)&ws[tx + 16 * j][k + 8];
            }
            FMA16(qvb, wvb)
        }
#undef FMA16

        // Epilogue: scale, relu, coalesced store to [seg][b][r].
        float* dst = g_cos + (size_t)seg * BATCH * NROWS;
#pragma unroll
        for (int i = 0; i < 4; i++) {
            int b = bbase + ty + 16 * i;
            float qi = qn[ty + 16 * i];
#pragma unroll
            for (int j = 0; j < 4; j++) {
                int r = rbase + tx + 16 * j;
                float v = acc[i][j] * qi * wn[tx + 16 * j];
                dst[(size_t)b * NROWS + r] = fmaxf(v, 0.0f);
            }
        }

        // Release this tile: stores -> fence -> barrier -> flag add.
        __threadfence();
        __syncthreads();
        if (tid == 0) atomicAdd(&g_ready[g], 1);
    }
}

// ---------------------------------------------------------------------------
// Kernel 2 (PDL secondary): combo-product expansion. Spins on its group's
// flag (8 seg tiles), then streams its 64-row chunk. High occupancy.
// ---------------------------------------------------------------------------
__global__ __launch_bounds__(256, 8) void combo_kernel(float* __restrict__ out) {
    __shared__ float cs[RCHUNK][NVECS];   // 2 KB

    int c   = blockIdx.x;
    int b   = c >> 2;
    int rq  = c & 3;
    int r0  = rq * RCHUNK;
    int grp = (b >> 6) * 4 + rq;          // matches dot group (b/64, r/64)
    int tid = threadIdx.x;

    // Acquire: wait for all 8 seg tiles of this group.
    if (tid == 0) {
        while (atomicAdd(&g_ready[grp], 0) < 8) __nanosleep(128);
    }
    __syncthreads();
    __threadfence();

    // Load this chunk's cos values: 8 contiguous 256B runs (one per seg).
    for (int i = tid; i < RCHUNK * NVECS; i += 256) {
        int seg = i >> 6;
        int rr  = i & 63;
        cs[rr][seg] = g_cos[(size_t)seg * BATCH * NROWS + (size_t)b * NROWS + r0 + rr];
    }
    __syncthreads();

    int sub   = tid & 63;   // combo quad: combos [4*sub, 4*sub+3]
    int rlane = tid >> 6;   // 0..3

    // Per-bit select constants: (bit? 1-v : v) == fmaf(sgn, v, off).
    float sgn[6], off[6];
#pragma unroll
    for (int j = 0; j < 6; j++) {
        int bit = (sub >> j) & 1;
        sgn[j] = bit ? -1.0f : 1.0f;
        off[j] = bit ? 1.0f : 0.0f;
    }

    float* ob = out + (size_t)b * NROWS * 256 + (size_t)r0 * 256;

#pragma unroll
    for (int rg = 0; rg < RCHUNK / 4; rg++) {
        int r = rg * 4 + rlane;
        float4 cA = *(const float4*)&cs[r][0];   // c0..c3
        float4 cB = *(const float4*)&cs[r][4];   // c4..c7

        float t2 = fmaf(sgn[0], cA.z, off[0]);
        float t3 = fmaf(sgn[1], cA.w, off[1]);
        float t4 = fmaf(sgn[2], cB.x, off[2]);
        float t5 = fmaf(sgn[3], cB.y, off[3]);
        float t6 = fmaf(sgn[4], cB.z, off[4]);
        float t7 = fmaf(sgn[5], cB.w, off[5]);
        float p  = ((t2 * t3) * (t4 * t5)) * (t6 * t7);

        float c0 = cA.x, c1 = cA.y;
        float n0 = 1.0f - c0;
        float pc1 = p * c1;
        float pn1 = p * (1.0f - c1);
        float4 o;
        o.x = pc1 * c0;    // combo bits (0,0)
        o.y = pc1 * n0;    // (1,0)
        o.z = pn1 * c0;    // (0,1)
        o.w = pn1 * n0;    // (1,1)

        __stcs((float4*)(ob + (size_t)r * 256) + sub, o);
    }

    // Cleanup for the next graph replay: last of this group's 64 combo CTAs
    // zeroes both counters (all readers have passed the spin by then).
    __syncthreads();
    if (tid == 0) {
        int old = atomicAdd(&g_done[grp], 1);
        if (old == 63) {
            g_done[grp]  = 0;
            g_ready[grp] = 0;
            __threadfence();
        }
    }
}

// ---------------------------------------------------------------------------
extern "C" void kernel_launch(void* const* d_in, const int* in_sizes, int n_in,
                              void* d_out, int out_size) {
    const float* query  = (const float*)d_in[0];   // [512, 1024]
    const float* weight = (const float*)d_in[1];   // [256, 1024]
    float* out = (float*)d_out;                    // [512, 256, 256]

    const int dot_smem = ((BM + BR) * PAD + BM + BR) * (int)sizeof(float); // ~68 KB
    (void)cudaFuncSetAttribute(dot_kernel,
                               cudaFuncAttributeMaxDynamicSharedMemorySize,
                               dot_smem);

    // Primary: plain launch (persistent, 2 rounds, progressive releases).
    dot_kernel<<<NDOT, 256, dot_smem>>>(query, weight);

    // Secondary: programmatic dependent launch -> co-runs with dot, gated by
    // per-group flags. Falls back to a plain (serialized) launch on error.
    cudaLaunchConfig_t cfg = {};
    cfg.gridDim  = dim3(NCOMBO);
    cfg.blockDim = dim3(256);
    cfg.dynamicSmemBytes = 0;
    cfg.stream = 0;
    cudaLaunchAttribute attr[1];
    attr[0].id = cudaLaunchAttributeProgrammaticStreamSerialization;
    attr[0].val.programmaticStreamSerializationAllowed = 1;
    cfg.attrs = attr;
    cfg.numAttrs = 1;
    cudaError_t e = cudaLaunchKernelEx(&cfg, combo_kernel, out);
    if (e != cudaSuccess) {
        combo_kernel<<<NCOMBO, 256>>>(out);
    }
}